// round 7
// baseline (speedup 1.0000x reference)
#include <cuda_runtime.h>

// LSTM T=4096, B=2048, I=2, H=4, L=4. Gate order i,f,g,o.
// lane = b*16 + l*4 + j : b = batch-in-warp (2), l = layer (4), j = unit (4).
// Each lane computes ALL FOUR gate rows of its unit locally -> cell update is
// thread-local. Only shuffles: quad h-gather (xor 1,2,3) + layer handoff
// (src = (lane-4)^m, width 16). Skewed wavefront: body(s) runs layer l at
// timestep s-l. Gather permutation folded into weight column order (j^m).
// Activation scales folded into weights/biases.

#define TT 4096
#define BB 2048

#define SGM (-1.4426950408889634f)   // -log2(e)
#define TGS (-2.8853900817779268f)   // -2*log2(e)

__device__ __forceinline__ float ex2f(float x) {
    float y; asm("ex2.approx.f32 %0, %1;" : "=f"(y) : "f"(x)); return y;
}
__device__ __forceinline__ float rcpf(float x) {
    float y; asm("rcp.approx.f32 %0, %1;" : "=f"(y) : "f"(x)); return y;
}

__global__ __launch_bounds__(32) void lstm_kernel(
    const float* __restrict__ x,     // (T, B, 2)
    const float* __restrict__ h0g,   // (L, B, 4)
    const float* __restrict__ c0g,   // (L, B, 4)
    const float* __restrict__ Wih0,  // (16, 2)
    const float* __restrict__ Wr,    // (3, 16, 4)  W_ih layers 1..3
    const float* __restrict__ Whh,   // (4, 16, 4)
    const float* __restrict__ bih,   // (4, 16)
    const float* __restrict__ bhh,   // (4, 16)
    float* __restrict__ out)         // ys (T,B,4) ++ hT (L,B,4) ++ cT (L,B,4)
{
    const int lane  = threadIdx.x & 31;
    const int b     = lane >> 4;              // batch sub-index 0..1
    const int l     = (lane >> 2) & 3;        // layer 0..3
    const int j     = lane & 3;               // hidden unit 0..3
    const int batch = blockIdx.x * 2 + b;

    // handoff source lanes (from previous layer's quad), computed once
    const int ps0 = lane - 4;
    const int ps1 = (lane - 4) ^ 1;
    const int ps2 = (lane - 4) ^ 2;
    const int ps3 = (lane - 4) ^ 3;

    // ---- weights: 4 gate rows of unit j in layer l (scales + perm folded) ----
    float win[4][4], wh[4][4], bz[4];
#pragma unroll
    for (int g4 = 0; g4 < 4; g4++) {
        const int   row = g4 * 4 + j;         // i_j, f_j, g_j, o_j
        const float sc  = (g4 == 2) ? TGS : SGM;
        if (l == 0) {
            win[g4][0] = Wih0[row * 2 + 0] * sc;
            win[g4][1] = Wih0[row * 2 + 1] * sc;
            win[g4][2] = 0.f; win[g4][3] = 0.f;
        } else {
#pragma unroll
            for (int m = 0; m < 4; m++)
                win[g4][m] = Wr[((l - 1) * 16 + row) * 4 + (j ^ m)] * sc;
        }
#pragma unroll
        for (int m = 0; m < 4; m++)
            wh[g4][m] = Whh[(l * 16 + row) * 4 + (j ^ m)] * sc;
        bz[g4] = (bih[l * 16 + row] + bhh[l * 16 + row]) * sc;
    }

    // ---- states ----
    float hown[4], hin[4], c;
#pragma unroll
    for (int m = 0; m < 4; m++) {
        hown[m] = h0g[(l * BB + batch) * 4 + (j ^ m)];
        hin[m]  = 0.f;
    }
    c = c0g[(l * BB + batch) * 4 + j];

    float* __restrict__ ys  = out;
    float* __restrict__ hso = out + (size_t)TT * BB * 4;
    float* __restrict__ cso = hso + (size_t)4 * BB * 4;

    float4* __restrict__ ysp = reinterpret_cast<float4*>(ys) + batch - 3 * BB;

    // ---- x stream (prefetch depth 3) ----
    const float* xb = x + batch * 2;
    float2 xa = *reinterpret_cast<const float2*>(xb);                       // x[0]
    float2 xn = *reinterpret_cast<const float2*>(xb + (size_t)1 * BB * 2);  // x[1]
    float2 xm = *reinterpret_cast<const float2*>(xb + (size_t)2 * BB * 2);  // x[2]
    if (l == 0) { hin[0] = xa.x; hin[1] = xa.y; }

    auto body = [&](int s, bool masked) {
        int tp = s + 3; if (tp > TT - 1) tp = TT - 1;
        float2 xf = *reinterpret_cast<const float2*>(xb + (size_t)tp * BB * 2);

        // ---- four gate pre-activations (two depth-4 chains each) ----
        float z[4];
#pragma unroll
        for (int g4 = 0; g4 < 4; g4++) {
            float u = fmaf(win[g4][0], hin[0],
                      fmaf(win[g4][1], hin[1], bz[g4]));
            u = fmaf(win[g4][2], hin[2], u);
            u = fmaf(win[g4][3], hin[3], u);
            float v = fmaf(wh[g4][0], hown[0], wh[g4][1] * hown[1]);
            v = fmaf(wh[g4][2], hown[2], v);
            v = fmaf(wh[g4][3], hown[3], v);
            z[g4] = u + v;
        }

        // ---- activations (scales pre-folded into z) ----
        float si = rcpf(1.0f + ex2f(z[0]));                     // sigma(i)
        float sf = rcpf(1.0f + ex2f(z[1]));                     // sigma(f)
        float tg = fmaf(rcpf(1.0f + ex2f(z[2])), 2.0f, -1.0f);  // tanh(g)
        float so = rcpf(1.0f + ex2f(z[3]));                     // sigma(o)

        float cn = fmaf(sf, c, si * tg);
        float th = fmaf(rcpf(1.0f + ex2f(cn * TGS)), 2.0f, -1.0f); // tanh(c)
        float h  = so * th;

        // ---- 7 independent shuffles, all sourced from h ----
        float h1 = __shfl_xor_sync(0xffffffffu, h, 1);
        float h2 = __shfl_xor_sync(0xffffffffu, h, 2);
        float h3 = __shfl_xor_sync(0xffffffffu, h, 3);
        float p0 = __shfl_sync(0xffffffffu, h, ps0, 16);
        float p1 = __shfl_sync(0xffffffffu, h, ps1, 16);
        float p2 = __shfl_sync(0xffffffffu, h, ps2, 16);
        float p3 = __shfl_sync(0xffffffffu, h, ps3, 16);

        bool act  = masked ? ((unsigned)(s - l)     < (unsigned)TT) : true;
        bool actp = masked ? ((unsigned)(s + 1 - l) < (unsigned)TT) : true;

        if (act) {
            c = cn;
            hown[0] = h;  hown[1] = h1; hown[2] = h2; hown[3] = h3;
            if (l == 3 && j == 0)
                *ysp = make_float4(h, h1, h2, h3);
        }
        ysp += BB;

        xa = xn; xn = xm; xm = xf;
        if (l == 0) { hin[0] = xa.x; hin[1] = xa.y; }
        else if (actp) { hin[0] = p0; hin[1] = p1; hin[2] = p2; hin[3] = p3; }
    };

    body(0, true); body(1, true); body(2, true);
#pragma unroll 1
    for (int s = 3; s < TT; s++) body(s, false);
    body(TT, true); body(TT + 1, true); body(TT + 2, true);

    // ---- final hT / cT ----
    if (j == 0)   // hown[m] = h_{0^m} = h_m natural order
        *reinterpret_cast<float4*>(hso + (l * BB + batch) * 4) =
            make_float4(hown[0], hown[1], hown[2], hown[3]);
    cso[(l * BB + batch) * 4 + j] = c;
}

extern "C" void kernel_launch(void* const* d_in, const int* in_sizes, int n_in,
                              void* d_out, int out_size) {
    (void)in_sizes; (void)n_in; (void)out_size;
    const float* x    = (const float*)d_in[0];
    const float* h0   = (const float*)d_in[1];
    const float* c0   = (const float*)d_in[2];
    const float* Wih0 = (const float*)d_in[3];
    const float* Wr   = (const float*)d_in[4];
    const float* Whh  = (const float*)d_in[5];
    const float* bih  = (const float*)d_in[6];
    const float* bhh  = (const float*)d_in[7];
    // 2 batches per warp, 1 warp per block: 1024 blocks -> 1024 warps
    lstm_kernel<<<BB / 2, 32>>>(x, h0, c0, Wih0, Wr, Whh, bih, bhh, (float*)d_out);
}

// round 8
// speedup vs baseline: 1.5581x; 1.5581x over previous
#include <cuda_runtime.h>

// LSTM T=4096, B=2048, I=2, H=4, L=4. Gate order i,f,g,o.
// lane = b*16 + l*4 + j : b = batch-in-warp (2), l = layer (4), j = unit (4).
// Each lane computes all 4 gate rows of its unit locally; cell update is
// thread-local. Shuffles: quad h-gather (xor 1,2,3) + layer handoff (4), all
// independent, all sourced from h. Skewed wavefront: body(s) runs layer l at
// step s-l. Activations: i/o via 0.5*tanh(x/2)+0.5 (weights pre-scaled 0.5),
// g and cell via tanh.approx; f-gate kept exact (ex2/rcp) to bound the
// compounding error in the c recurrence.

#define TT 4096
#define BB 2048

#define SGM (-1.4426950408889634f)   // -log2(e)  (f gate, exact sigmoid)

__device__ __forceinline__ float ex2f(float x) {
    float y; asm("ex2.approx.f32 %0, %1;" : "=f"(y) : "f"(x)); return y;
}
__device__ __forceinline__ float rcpf(float x) {
    float y; asm("rcp.approx.f32 %0, %1;" : "=f"(y) : "f"(x)); return y;
}
__device__ __forceinline__ float tanhx(float x) {
    float y; asm("tanh.approx.f32 %0, %1;" : "=f"(y) : "f"(x)); return y;
}

__global__ __launch_bounds__(32) void lstm_kernel(
    const float* __restrict__ x,     // (T, B, 2)
    const float* __restrict__ h0g,   // (L, B, 4)
    const float* __restrict__ c0g,   // (L, B, 4)
    const float* __restrict__ Wih0,  // (16, 2)
    const float* __restrict__ Wr,    // (3, 16, 4)  W_ih layers 1..3
    const float* __restrict__ Whh,   // (4, 16, 4)
    const float* __restrict__ bih,   // (4, 16)
    const float* __restrict__ bhh,   // (4, 16)
    float* __restrict__ out)         // ys (T,B,4) ++ hT (L,B,4) ++ cT (L,B,4)
{
    const int lane  = threadIdx.x & 31;
    const int b     = lane >> 4;              // batch sub-index 0..1
    const int l     = (lane >> 2) & 3;        // layer 0..3
    const int j     = lane & 3;               // hidden unit 0..3
    const int batch = blockIdx.x * 2 + b;

    // handoff source lanes (previous layer's quad)
    const int ps0 = lane - 4;
    const int ps1 = (lane - 4) ^ 1;
    const int ps2 = (lane - 4) ^ 2;
    const int ps3 = (lane - 4) ^ 3;

    // ---- weights: 4 gate rows of unit j in layer l ----
    // per-gate pre-scale: i -> 0.5 (sigmoid-via-tanh), f -> -log2e (exact
    // sigmoid via ex2/rcp), g -> 1 (tanh), o -> 0.5.
    float win[4][4], wh[4][4], bz[4];
#pragma unroll
    for (int g4 = 0; g4 < 4; g4++) {
        const int   row = g4 * 4 + j;         // i_j, f_j, g_j, o_j
        const float sc  = (g4 == 1) ? SGM : ((g4 == 2) ? 1.0f : 0.5f);
        if (l == 0) {
            win[g4][0] = Wih0[row * 2 + 0] * sc;
            win[g4][1] = Wih0[row * 2 + 1] * sc;
            win[g4][2] = 0.f; win[g4][3] = 0.f;
        } else {
#pragma unroll
            for (int m = 0; m < 4; m++)
                win[g4][m] = Wr[((l - 1) * 16 + row) * 4 + (j ^ m)] * sc;
        }
#pragma unroll
        for (int m = 0; m < 4; m++)
            wh[g4][m] = Whh[(l * 16 + row) * 4 + (j ^ m)] * sc;
        bz[g4] = (bih[l * 16 + row] + bhh[l * 16 + row]) * sc;
    }

    // ---- states ----
    float hown[4], hin[4], c;
#pragma unroll
    for (int m = 0; m < 4; m++) {
        hown[m] = h0g[(l * BB + batch) * 4 + (j ^ m)];
        hin[m]  = 0.f;
    }
    c = c0g[(l * BB + batch) * 4 + j];

    float* __restrict__ ys  = out;
    float* __restrict__ hso = out + (size_t)TT * BB * 4;
    float* __restrict__ cso = hso + (size_t)4 * BB * 4;

    float4* __restrict__ ysp = reinterpret_cast<float4*>(ys) + batch - 3 * BB;

    // ---- x stream (prefetch depth 3) ----
    const float* xb = x + batch * 2;
    float2 xa = *reinterpret_cast<const float2*>(xb);                       // x[0]
    float2 xn = *reinterpret_cast<const float2*>(xb + (size_t)1 * BB * 2);  // x[1]
    float2 xm = *reinterpret_cast<const float2*>(xb + (size_t)2 * BB * 2);  // x[2]
    if (l == 0) { hin[0] = xa.x; hin[1] = xa.y; }

    auto body = [&](int s, bool masked) {
        int tp = s + 3; if (tp > TT - 1) tp = TT - 1;
        float2 xf = *reinterpret_cast<const float2*>(xb + (size_t)tp * BB * 2);

        // ---- four gate pre-activations (two depth-4 chains each) ----
        float z[4];
#pragma unroll
        for (int g4 = 0; g4 < 4; g4++) {
            float u = fmaf(win[g4][0], hin[0],
                      fmaf(win[g4][1], hin[1], bz[g4]));
            u = fmaf(win[g4][2], hin[2], u);
            u = fmaf(win[g4][3], hin[3], u);
            float v = fmaf(wh[g4][0], hown[0], wh[g4][1] * hown[1]);
            v = fmaf(wh[g4][2], hown[2], v);
            v = fmaf(wh[g4][3], hown[3], v);
            z[g4] = u + v;
        }

        // ---- activations ----
        float si = fmaf(tanhx(z[0]), 0.5f, 0.5f);   // sigma(i), approx
        float sf = rcpf(1.0f + ex2f(z[1]));         // sigma(f), exact
        float tg = tanhx(z[2]);                     // tanh(g),  approx
        float so = fmaf(tanhx(z[3]), 0.5f, 0.5f);   // sigma(o), approx

        float cn = fmaf(sf, c, si * tg);
        float th = tanhx(cn);                       // tanh(c),  approx
        float h  = so * th;

        // ---- 7 independent shuffles, all sourced from h ----
        float h1 = __shfl_xor_sync(0xffffffffu, h, 1);
        float h2 = __shfl_xor_sync(0xffffffffu, h, 2);
        float h3 = __shfl_xor_sync(0xffffffffu, h, 3);
        float p0 = __shfl_sync(0xffffffffu, h, ps0, 16);
        float p1 = __shfl_sync(0xffffffffu, h, ps1, 16);
        float p2 = __shfl_sync(0xffffffffu, h, ps2, 16);
        float p3 = __shfl_sync(0xffffffffu, h, ps3, 16);

        bool act  = masked ? ((unsigned)(s - l)     < (unsigned)TT) : true;
        bool actp = masked ? ((unsigned)(s + 1 - l) < (unsigned)TT) : true;

        if (act) {
            c = cn;
            hown[0] = h;  hown[1] = h1; hown[2] = h2; hown[3] = h3;
            if (l == 3 && j == 0)
                *ysp = make_float4(h, h1, h2, h3);
        }
        ysp += BB;

        xa = xn; xn = xm; xm = xf;
        if (l == 0) { hin[0] = xa.x; hin[1] = xa.y; }
        else if (actp) { hin[0] = p0; hin[1] = p1; hin[2] = p2; hin[3] = p3; }
    };

    body(0, true); body(1, true); body(2, true);
#pragma unroll 2
    for (int s = 3; s < TT; s++) body(s, false);
    body(TT, true); body(TT + 1, true); body(TT + 2, true);

    // ---- final hT / cT ----
    if (j == 0)   // hown[m] = h_m natural order for j==0
        *reinterpret_cast<float4*>(hso + (l * BB + batch) * 4) =
            make_float4(hown[0], hown[1], hown[2], hown[3]);
    cso[(l * BB + batch) * 4 + j] = c;
}

extern "C" void kernel_launch(void* const* d_in, const int* in_sizes, int n_in,
                              void* d_out, int out_size) {
    (void)in_sizes; (void)n_in; (void)out_size;
    const float* x    = (const float*)d_in[0];
    const float* h0   = (const float*)d_in[1];
    const float* c0   = (const float*)d_in[2];
    const float* Wih0 = (const float*)d_in[3];
    const float* Wr   = (const float*)d_in[4];
    const float* Whh  = (const float*)d_in[5];
    const float* bih  = (const float*)d_in[6];
    const float* bhh  = (const float*)d_in[7];
    // 2 batches per warp, 1 warp per block: 1024 blocks -> 1024 warps
    lstm_kernel<<<BB / 2, 32>>>(x, h0, c0, Wih0, Wr, Whh, bih, bhh, (float*)d_out);
}